// round 13
// baseline (speedup 1.0000x reference)
#include <cuda_runtime.h>
#include <cstdint>

// Conv(5x5, SAME) over [256,1,512,512] + FastLIF + FastLI temporal scan.
// ONE WARP PER BLOCK, tile 32x8 (grid 16x64 = 1024 blocks), each thread
// 2 rows x 4 cols. Time loop UNROLLED BY 4: one wait_group + one __syncwarp
// per FOUR timesteps. Register pressure bounded by processing the 4 steps
// as two conv-pairs (conv,conv,LIF,store twice). 12 smem buffers: 4 read,
// 4 in flight, 4 filling (cp.async zfill OOB, rotation-safe scratch).

#define TT 256
#define HH 512
#define WW 512
#define HW (HH*WW)

#define QW 32        // tile width (outputs)
#define QH 8         // tile height (outputs)
#define NT 32        // threads per block (1 warp)
#define SWP 40       // smem row stride (32+8 halo cols)
#define SHR 12       // smem rows (8+4 halo)
#define WBUF (SHR*SWP)        // 480 floats used per buffer
#define WBUFP (WBUF + 4)      // +4 floats per-buffer scratch (zfill dump)
#define NBUF 12
#define F4R 10                // float4 per smem row
#define FILLV (SHR*F4R)       // 120 float4 copies per tile
#define PF 4                  // ceil(120/32) fill slots per lane

#define ALPHA_LIF 0.85f
#define V_TH 2.0f
#define ALPHA_LI 0.9f

__device__ __forceinline__ void cp_async16(uint32_t dst_smem, const void* src, int srcsize) {
    asm volatile("cp.async.cg.shared.global [%0], [%1], 16, %2;\n"
                 :: "r"(dst_smem), "l"(src), "r"(srcsize));
}
__device__ __forceinline__ void cp_commit() {
    asm volatile("cp.async.commit_group;\n");
}
__device__ __forceinline__ void cp_wait4() {
    asm volatile("cp.async.wait_group 4;\n");
}

// 5x5 conv for 2 rows x 4 cols from 6 streamed smem rows (3x LDS.128 each)
__device__ __forceinline__ void conv8(const float* __restrict__ rb,
                                      const float* __restrict__ wgt,
                                      float* __restrict__ acc)
{
    float a0 = 0.f, a1 = 0.f, a2 = 0.f, a3 = 0.f;
    float d0 = 0.f, d1 = 0.f, d2 = 0.f, d3 = 0.f;
#pragma unroll
    for (int j = 0; j < 6; j++) {
        const float* rp = rb + j * SWP;
        float4 q0 = *(const float4*)(rp + 0);
        float4 q1 = *(const float4*)(rp + 4);
        float4 q2 = *(const float4*)(rp + 8);
        float m0 = q0.z, m1 = q0.w, m2 = q1.x, m3 = q1.y;
        float m4 = q1.z, m5 = q1.w, m6 = q2.x, m7 = q2.y;
        if (j < 5) {                     // upper row, vertical tap a=j
            const float* wa = wgt + j * 5;
            a0 = fmaf(wa[0], m0, a0); a0 = fmaf(wa[1], m1, a0);
            a0 = fmaf(wa[2], m2, a0); a0 = fmaf(wa[3], m3, a0);
            a0 = fmaf(wa[4], m4, a0);
            a1 = fmaf(wa[0], m1, a1); a1 = fmaf(wa[1], m2, a1);
            a1 = fmaf(wa[2], m3, a1); a1 = fmaf(wa[3], m4, a1);
            a1 = fmaf(wa[4], m5, a1);
            a2 = fmaf(wa[0], m2, a2); a2 = fmaf(wa[1], m3, a2);
            a2 = fmaf(wa[2], m4, a2); a2 = fmaf(wa[3], m5, a2);
            a2 = fmaf(wa[4], m6, a2);
            a3 = fmaf(wa[0], m3, a3); a3 = fmaf(wa[1], m4, a3);
            a3 = fmaf(wa[2], m5, a3); a3 = fmaf(wa[3], m6, a3);
            a3 = fmaf(wa[4], m7, a3);
        }
        if (j > 0) {                     // lower row, vertical tap a=j-1
            const float* wb = wgt + (j - 1) * 5;
            d0 = fmaf(wb[0], m0, d0); d0 = fmaf(wb[1], m1, d0);
            d0 = fmaf(wb[2], m2, d0); d0 = fmaf(wb[3], m3, d0);
            d0 = fmaf(wb[4], m4, d0);
            d1 = fmaf(wb[0], m1, d1); d1 = fmaf(wb[1], m2, d1);
            d1 = fmaf(wb[2], m3, d1); d1 = fmaf(wb[3], m4, d1);
            d1 = fmaf(wb[4], m5, d1);
            d2 = fmaf(wb[0], m2, d2); d2 = fmaf(wb[1], m3, d2);
            d2 = fmaf(wb[2], m4, d2); d2 = fmaf(wb[3], m5, d2);
            d2 = fmaf(wb[4], m6, d2);
            d3 = fmaf(wb[0], m3, d3); d3 = fmaf(wb[1], m4, d3);
            d3 = fmaf(wb[2], m5, d3); d3 = fmaf(wb[3], m6, d3);
            d3 = fmaf(wb[4], m7, d3);
        }
    }
    acc[0] = a0; acc[1] = a1; acc[2] = a2; acc[3] = a3;
    acc[4] = d0; acc[5] = d1; acc[6] = d2; acc[7] = d3;
}

__global__ __launch_bounds__(NT)
void snn_fused_kernel(const float* __restrict__ x,
                      const float* __restrict__ kern,
                      float* __restrict__ out)
{
    __shared__ __align__(16) float sm[NBUF * WBUFP];

    const int lane = threadIdx.x;
    const int tc   = lane & 7;        // col group: output cols x0+4tc .. +3
    const int rgL  = lane >> 3;       // row-pair group: rows y0+2rgL, +1

    const int x0 = blockIdx.x * QW;
    const int y0 = blockIdx.y * QH;

    // 5x5 weights in registers (uniform broadcast)
    float wgt[25];
#pragma unroll
    for (int i = 0; i < 25; i++) wgt[i] = __ldg(kern + i);

    // ---- Precompute this lane's PF cp.async fill slots (invariant over t) ----
    // Slot j copies float4 #(lane + j*32) of the 12-row x 10-float4 tile.
    // smem col 0 <-> global col x0-4 ; smem row 0 <-> global row y0-2.
    // Inactive slots target the per-buffer scratch at offset WBUF.
    int soff[PF], goff[PF], ssz[PF];
#pragma unroll
    for (int j = 0; j < PF; j++) {
        int i = lane + j * 32;
        if (i < FILLV) {
            int rr = i / F4R;
            int c4 = i - rr * F4R;
            int gy = y0 - 2 + rr;
            int gx = x0 - 4 + 4 * c4;
            bool v = (gy >= 0) && (gy < HH) && (gx >= 0) && (gx <= WW - 4);
            soff[j] = rr * SWP + 4 * c4;
            goff[j] = v ? (gy * WW + gx) : 0;
            ssz[j]  = v ? 16 : 0;
        } else {
            soff[j] = WBUF;   // per-buffer scratch, rotation-safe
            goff[j] = 0;
            ssz[j]  = 0;
        }
    }

    const uint32_t cb = (uint32_t)__cvta_generic_to_shared(&sm[0]);

    // ---- Prologue: prefetch timesteps 0..7 into buffers 0..7 (8 groups) ----
#pragma unroll
    for (int q = 0; q < 8; q++) {
        const float* xt = x + (size_t)q * HW;
        uint32_t dst = cb + (uint32_t)q * (4u * WBUFP);
#pragma unroll
        for (int j = 0; j < PF; j++) cp_async16(dst + 4u * soff[j], xt + goff[j], ssz[j]);
        cp_commit();
    }

    // LIF / LI state: 2 rows x 4 cols
    float s1[8], s2[8];
#pragma unroll
    for (int i = 0; i < 8; i++) { s1[i] = 0.f; s2[i] = 0.f; }

    const float* xp = x + 8 * (size_t)HW;                         // source for t+8
    float* op = out + (size_t)(y0 + 2 * rgL) * WW + x0 + 4 * tc;  // row 0 of pair
    const int rbase = (2 * rgL) * SWP + 4 * tc;                   // smem read base
    int rbuf = 0;                                                 // buffer of step t

    for (int t = 0; t < TT; t += 4) {
        cp_wait4();      // groups t..t+3 complete (t+4..t+7 may be pending)
        __syncwarp();    // cross-lane visibility of this iteration's tiles

        // Prefetch t+8..t+11 into the four buffers freed last iteration
        {
#pragma unroll
            for (int q = 0; q < 4; q++) {
                int bq = rbuf + 8 + q; if (bq >= NBUF) bq -= NBUF;
                if (t + 8 + q < TT) {
                    uint32_t dst = cb + (uint32_t)bq * (4u * WBUFP);
                    const float* xs = xp + (size_t)q * HW;
#pragma unroll
                    for (int j = 0; j < PF; j++)
                        cp_async16(dst + 4u * soff[j], xs + goff[j], ssz[j]);
                }
                cp_commit();   // unconditional: uniform wait_group accounting
            }
            xp += 4 * (size_t)HW;
        }

        // ---- Steps t, t+1 (two independent convs = 16 FMA chains) ----
        {
            int rb1 = rbuf + 1; if (rb1 >= NBUF) rb1 -= NBUF;
            float accA[8], accB[8];
            conv8(&sm[rbase + rbuf * WBUFP], wgt, accA);
            conv8(&sm[rbase + rb1  * WBUFP], wgt, accB);

            float oA[8], oB[8];
#pragma unroll
            for (int i = 0; i < 8; i++) {
                float v = fmaf(ALPHA_LIF, s1[i], accA[i]);
                float spk = (v >= V_TH) ? 1.0f : 0.0f;
                s1[i] = fmaf(spk, -V_TH, v);
                s2[i] = fmaf(ALPHA_LI, s2[i], spk);
                oA[i] = s2[i];
                float v2 = fmaf(ALPHA_LIF, s1[i], accB[i]);
                float spk2 = (v2 >= V_TH) ? 1.0f : 0.0f;
                s1[i] = fmaf(spk2, -V_TH, v2);
                s2[i] = fmaf(ALPHA_LI, s2[i], spk2);
                oB[i] = s2[i];
            }
            float4 v0 = {oA[0], oA[1], oA[2], oA[3]};
            float4 v1 = {oA[4], oA[5], oA[6], oA[7]};
            float4 v2 = {oB[0], oB[1], oB[2], oB[3]};
            float4 v3 = {oB[4], oB[5], oB[6], oB[7]};
            *(float4*)op = v0;
            *(float4*)(op + WW) = v1;
            *(float4*)(op + HW) = v2;
            *(float4*)(op + HW + WW) = v3;
        }

        // ---- Steps t+2, t+3 ----
        {
            int rb2 = rbuf + 2; if (rb2 >= NBUF) rb2 -= NBUF;
            int rb3 = rbuf + 3; if (rb3 >= NBUF) rb3 -= NBUF;
            float accC[8], accD[8];
            conv8(&sm[rbase + rb2 * WBUFP], wgt, accC);
            conv8(&sm[rbase + rb3 * WBUFP], wgt, accD);

            float oC[8], oD[8];
#pragma unroll
            for (int i = 0; i < 8; i++) {
                float v = fmaf(ALPHA_LIF, s1[i], accC[i]);
                float spk = (v >= V_TH) ? 1.0f : 0.0f;
                s1[i] = fmaf(spk, -V_TH, v);
                s2[i] = fmaf(ALPHA_LI, s2[i], spk);
                oC[i] = s2[i];
                float v2 = fmaf(ALPHA_LIF, s1[i], accD[i]);
                float spk2 = (v2 >= V_TH) ? 1.0f : 0.0f;
                s1[i] = fmaf(spk2, -V_TH, v2);
                s2[i] = fmaf(ALPHA_LI, s2[i], spk2);
                oD[i] = s2[i];
            }
            float4 v0 = {oC[0], oC[1], oC[2], oC[3]};
            float4 v1 = {oC[4], oC[5], oC[6], oC[7]};
            float4 v2 = {oD[0], oD[1], oD[2], oD[3]};
            float4 v3 = {oD[4], oD[5], oD[6], oD[7]};
            float* op2 = op + 2 * (size_t)HW;
            *(float4*)op2 = v0;
            *(float4*)(op2 + WW) = v1;
            *(float4*)(op2 + HW) = v2;
            *(float4*)(op2 + HW + WW) = v3;
        }

        op += 4 * (size_t)HW;
        rbuf += 4; if (rbuf >= NBUF) rbuf -= NBUF;
    }
}

extern "C" void kernel_launch(void* const* d_in, const int* in_sizes, int n_in,
                              void* d_out, int out_size)
{
    const float* x = (const float*)d_in[0];
    const float* k = (const float*)d_in[1];
    if (in_sizes[0] == 25) {  // defensive: swap if metadata order differs
        const float* tmp = x; x = k; k = tmp;
    }
    float* out = (float*)d_out;

    dim3 grid(WW / QW, HH / QH);   // 16 x 64 = 1024 one-warp blocks
    snn_fused_kernel<<<grid, NT>>>(x, k, out);
}

// round 14
// speedup vs baseline: 1.0088x; 1.0088x over previous
#include <cuda_runtime.h>
#include <cstdint>

// Conv(5x5, SAME) over [256,1,512,512] + FastLIF + FastLI temporal scan.
// ONE WARP PER BLOCK, tile 32x8 (grid 16x64 = 1024 blocks), each thread
// 2 rows x 4 cols. Time loop unrolled by 2 with:
//  - prefetch ISSUED BEFORE the wait (wait_group 4 after issuing 2 new
//    groups == old wait_group 2 before), so new LDGSTS fly during the stall
//  - the two timesteps' convs INTERLEAVED in one j-loop (6 LDS.128 then
//    80 FMAs per iteration) for maximum LDS->use distance.
// 6 smem buffers, cp.async zfill OOB, rotation-safe per-buffer scratch.

#define TT 256
#define HH 512
#define WW 512
#define HW (HH*WW)

#define QW 32        // tile width (outputs)
#define QH 8         // tile height (outputs)
#define NT 32        // threads per block (1 warp)
#define SWP 40       // smem row stride (32+8 halo cols)
#define SHR 12       // smem rows (8+4 halo)
#define WBUF (SHR*SWP)        // 480 floats used per buffer
#define WBUFP (WBUF + 4)      // +4 floats per-buffer scratch (zfill dump)
#define NBUF 6
#define F4R 10                // float4 per smem row
#define FILLV (SHR*F4R)       // 120 float4 copies per tile
#define PF 4                  // ceil(120/32) fill slots per lane

#define ALPHA_LIF 0.85f
#define V_TH 2.0f
#define ALPHA_LI 0.9f

__device__ __forceinline__ void cp_async16(uint32_t dst_smem, const void* src, int srcsize) {
    asm volatile("cp.async.cg.shared.global [%0], [%1], 16, %2;\n"
                 :: "r"(dst_smem), "l"(src), "r"(srcsize));
}
__device__ __forceinline__ void cp_commit() {
    asm volatile("cp.async.commit_group;\n");
}
__device__ __forceinline__ void cp_wait4() {
    asm volatile("cp.async.wait_group 4;\n");
}

__global__ __launch_bounds__(NT)
void snn_fused_kernel(const float* __restrict__ x,
                      const float* __restrict__ kern,
                      float* __restrict__ out)
{
    __shared__ __align__(16) float sm[NBUF * WBUFP];

    const int lane = threadIdx.x;
    const int tc   = lane & 7;        // col group: output cols x0+4tc .. +3
    const int rgL  = lane >> 3;       // row-pair group: rows y0+2rgL, +1

    const int x0 = blockIdx.x * QW;
    const int y0 = blockIdx.y * QH;

    // 5x5 weights in registers (uniform broadcast)
    float wgt[25];
#pragma unroll
    for (int i = 0; i < 25; i++) wgt[i] = __ldg(kern + i);

    // ---- Precompute this lane's PF cp.async fill slots (invariant over t) ----
    int soff[PF], goff[PF], ssz[PF];
#pragma unroll
    for (int j = 0; j < PF; j++) {
        int i = lane + j * 32;
        if (i < FILLV) {
            int rr = i / F4R;
            int c4 = i - rr * F4R;
            int gy = y0 - 2 + rr;
            int gx = x0 - 4 + 4 * c4;
            bool v = (gy >= 0) && (gy < HH) && (gx >= 0) && (gx <= WW - 4);
            soff[j] = rr * SWP + 4 * c4;
            goff[j] = v ? (gy * WW + gx) : 0;
            ssz[j]  = v ? 16 : 0;
        } else {
            soff[j] = WBUF;   // per-buffer scratch, rotation-safe
            goff[j] = 0;
            ssz[j]  = 0;
        }
    }

    const uint32_t cb = (uint32_t)__cvta_generic_to_shared(&sm[0]);

    // ---- Prologue: prefetch timesteps 0..3 into buffers 0..3 ----
#pragma unroll
    for (int q = 0; q < 4; q++) {
        const float* xt = x + (size_t)q * HW;
        uint32_t dst = cb + (uint32_t)q * (4u * WBUFP);
#pragma unroll
        for (int j = 0; j < PF; j++) cp_async16(dst + 4u * soff[j], xt + goff[j], ssz[j]);
        cp_commit();
    }

    // LIF / LI state: 2 rows x 4 cols
    float s1[8], s2[8];
#pragma unroll
    for (int i = 0; i < 8; i++) { s1[i] = 0.f; s2[i] = 0.f; }

    const float* xp = x + 4 * (size_t)HW;                         // source for t+4
    float* op = out + (size_t)(y0 + 2 * rgL) * WW + x0 + 4 * tc;  // row 0 of pair
    const int rbase = (2 * rgL) * SWP + 4 * tc;                   // smem read base
    int rbuf = 0;                                                 // buffer of step t

    for (int t = 0; t < TT; t += 2) {
        // ---- Issue prefetch of t+4, t+5 FIRST (into buffers freed last iter) ----
        {
            int b4 = rbuf + 4; if (b4 >= NBUF) b4 -= NBUF;
            int b5 = rbuf + 5; if (b5 >= NBUF) b5 -= NBUF;
            if (t + 4 < TT) {
                uint32_t dst = cb + (uint32_t)b4 * (4u * WBUFP);
#pragma unroll
                for (int j = 0; j < PF; j++)
                    cp_async16(dst + 4u * soff[j], xp + goff[j], ssz[j]);
            }
            cp_commit();
            if (t + 5 < TT) {
                uint32_t dst = cb + (uint32_t)b5 * (4u * WBUFP);
#pragma unroll
                for (int j = 0; j < PF; j++)
                    cp_async16(dst + 4u * soff[j], xp + HW + goff[j], ssz[j]);
            }
            cp_commit();
            xp += 2 * (size_t)HW;
        }

        // Wait until only the 4 newest groups (t+2..t+5) may be pending:
        // groups t and t+1 are then complete -> their tiles are readable.
        cp_wait4();
        __syncwarp();    // cross-lane visibility of tiles t, t+1

        // ---- Interleaved convs for steps t and t+1 (16 parallel chains) ----
        int rb1 = rbuf + 1; if (rb1 >= NBUF) rb1 -= NBUF;
        const float* rbA = &sm[rbase + rbuf * WBUFP];
        const float* rbB = &sm[rbase + rb1  * WBUFP];

        float aA0=0.f,aA1=0.f,aA2=0.f,aA3=0.f, dA0=0.f,dA1=0.f,dA2=0.f,dA3=0.f;
        float aB0=0.f,aB1=0.f,aB2=0.f,aB3=0.f, dB0=0.f,dB1=0.f,dB2=0.f,dB3=0.f;
#pragma unroll
        for (int j = 0; j < 6; j++) {
            const float* rpA = rbA + j * SWP;
            const float* rpB = rbB + j * SWP;
            float4 pA0 = *(const float4*)(rpA + 0);
            float4 pA1 = *(const float4*)(rpA + 4);
            float4 pA2 = *(const float4*)(rpA + 8);
            float4 pB0 = *(const float4*)(rpB + 0);
            float4 pB1 = *(const float4*)(rpB + 4);
            float4 pB2 = *(const float4*)(rpB + 8);
            float A0 = pA0.z, A1 = pA0.w, A2 = pA1.x, A3 = pA1.y;
            float A4 = pA1.z, A5 = pA1.w, A6 = pA2.x, A7 = pA2.y;
            float B0 = pB0.z, B1 = pB0.w, B2 = pB1.x, B3 = pB1.y;
            float B4 = pB1.z, B5 = pB1.w, B6 = pB2.x, B7 = pB2.y;
            if (j < 5) {                     // upper rows, vertical tap a=j
                const float* wa = wgt + j * 5;
                aA0 = fmaf(wa[0], A0, aA0); aB0 = fmaf(wa[0], B0, aB0);
                aA0 = fmaf(wa[1], A1, aA0); aB0 = fmaf(wa[1], B1, aB0);
                aA0 = fmaf(wa[2], A2, aA0); aB0 = fmaf(wa[2], B2, aB0);
                aA0 = fmaf(wa[3], A3, aA0); aB0 = fmaf(wa[3], B3, aB0);
                aA0 = fmaf(wa[4], A4, aA0); aB0 = fmaf(wa[4], B4, aB0);
                aA1 = fmaf(wa[0], A1, aA1); aB1 = fmaf(wa[0], B1, aB1);
                aA1 = fmaf(wa[1], A2, aA1); aB1 = fmaf(wa[1], B2, aB1);
                aA1 = fmaf(wa[2], A3, aA1); aB1 = fmaf(wa[2], B3, aB1);
                aA1 = fmaf(wa[3], A4, aA1); aB1 = fmaf(wa[3], B4, aB1);
                aA1 = fmaf(wa[4], A5, aA1); aB1 = fmaf(wa[4], B5, aB1);
                aA2 = fmaf(wa[0], A2, aA2); aB2 = fmaf(wa[0], B2, aB2);
                aA2 = fmaf(wa[1], A3, aA2); aB2 = fmaf(wa[1], B3, aB2);
                aA2 = fmaf(wa[2], A4, aA2); aB2 = fmaf(wa[2], B4, aB2);
                aA2 = fmaf(wa[3], A5, aA2); aB2 = fmaf(wa[3], B5, aB2);
                aA2 = fmaf(wa[4], A6, aA2); aB2 = fmaf(wa[4], B6, aB2);
                aA3 = fmaf(wa[0], A3, aA3); aB3 = fmaf(wa[0], B3, aB3);
                aA3 = fmaf(wa[1], A4, aA3); aB3 = fmaf(wa[1], B4, aB3);
                aA3 = fmaf(wa[2], A5, aA3); aB3 = fmaf(wa[2], B5, aB3);
                aA3 = fmaf(wa[3], A6, aA3); aB3 = fmaf(wa[3], B6, aB3);
                aA3 = fmaf(wa[4], A7, aA3); aB3 = fmaf(wa[4], B7, aB3);
            }
            if (j > 0) {                     // lower rows, vertical tap a=j-1
                const float* wb = wgt + (j - 1) * 5;
                dA0 = fmaf(wb[0], A0, dA0); dB0 = fmaf(wb[0], B0, dB0);
                dA0 = fmaf(wb[1], A1, dA0); dB0 = fmaf(wb[1], B1, dB0);
                dA0 = fmaf(wb[2], A2, dA0); dB0 = fmaf(wb[2], B2, dB0);
                dA0 = fmaf(wb[3], A3, dA0); dB0 = fmaf(wb[3], B3, dB0);
                dA0 = fmaf(wb[4], A4, dA0); dB0 = fmaf(wb[4], B4, dB0);
                dA1 = fmaf(wb[0], A1, dA1); dB1 = fmaf(wb[0], B1, dB1);
                dA1 = fmaf(wb[1], A2, dA1); dB1 = fmaf(wb[1], B2, dB1);
                dA1 = fmaf(wb[2], A3, dA1); dB1 = fmaf(wb[2], B3, dB1);
                dA1 = fmaf(wb[3], A4, dA1); dB1 = fmaf(wb[3], B4, dB1);
                dA1 = fmaf(wb[4], A5, dA1); dB1 = fmaf(wb[4], B5, dB1);
                dA2 = fmaf(wb[0], A2, dA2); dB2 = fmaf(wb[0], B2, dB2);
                dA2 = fmaf(wb[1], A3, dA2); dB2 = fmaf(wb[1], B3, dB2);
                dA2 = fmaf(wb[2], A4, dA2); dB2 = fmaf(wb[2], B4, dB2);
                dA2 = fmaf(wb[3], A5, dA2); dB2 = fmaf(wb[3], B5, dB2);
                dA2 = fmaf(wb[4], A6, dA2); dB2 = fmaf(wb[4], B6, dB2);
                dA3 = fmaf(wb[0], A3, dA3); dB3 = fmaf(wb[0], B3, dB3);
                dA3 = fmaf(wb[1], A4, dA3); dB3 = fmaf(wb[1], B4, dB3);
                dA3 = fmaf(wb[2], A5, dA3); dB3 = fmaf(wb[2], B5, dB3);
                dA3 = fmaf(wb[3], A6, dA3); dB3 = fmaf(wb[3], B6, dB3);
                dA3 = fmaf(wb[4], A7, dA3); dB3 = fmaf(wb[4], B7, dB3);
            }
        }

        // ---- LIF + LI for step t, then t+1 (sequential state) ----
        float accA[8] = {aA0, aA1, aA2, aA3, dA0, dA1, dA2, dA3};
        float accB[8] = {aB0, aB1, aB2, aB3, dB0, dB1, dB2, dB3};
        float oA[8], oB[8];
#pragma unroll
        for (int i = 0; i < 8; i++) {
            float v = fmaf(ALPHA_LIF, s1[i], accA[i]);
            float spk = (v >= V_TH) ? 1.0f : 0.0f;
            s1[i] = fmaf(spk, -V_TH, v);
            s2[i] = fmaf(ALPHA_LI, s2[i], spk);
            oA[i] = s2[i];
            float v2 = fmaf(ALPHA_LIF, s1[i], accB[i]);
            float spk2 = (v2 >= V_TH) ? 1.0f : 0.0f;
            s1[i] = fmaf(spk2, -V_TH, v2);
            s2[i] = fmaf(ALPHA_LI, s2[i], spk2);
            oB[i] = s2[i];
        }

        // ---- Stores: 2 rows x 2 steps, vectorized ----
        float4 v0 = {oA[0], oA[1], oA[2], oA[3]};
        float4 v1 = {oA[4], oA[5], oA[6], oA[7]};
        float4 v2 = {oB[0], oB[1], oB[2], oB[3]};
        float4 v3 = {oB[4], oB[5], oB[6], oB[7]};
        *(float4*)op = v0;
        *(float4*)(op + WW) = v1;
        *(float4*)(op + HW) = v2;
        *(float4*)(op + HW + WW) = v3;
        op += 2 * (size_t)HW;

        rbuf += 2; if (rbuf >= NBUF) rbuf -= NBUF;
    }
}

extern "C" void kernel_launch(void* const* d_in, const int* in_sizes, int n_in,
                              void* d_out, int out_size)
{
    const float* x = (const float*)d_in[0];
    const float* k = (const float*)d_in[1];
    if (in_sizes[0] == 25) {  // defensive: swap if metadata order differs
        const float* tmp = x; x = k; k = tmp;
    }
    float* out = (float*)d_out;

    dim3 grid(WW / QW, HH / QH);   // 16 x 64 = 1024 one-warp blocks
    snn_fused_kernel<<<grid, NT>>>(x, k, out);
}